// round 8
// baseline (speedup 1.0000x reference)
#include <cuda_runtime.h>
#include <cuda_fp16.h>
#include <math.h>
#include <stdint.h>

#define NN 8192
#define DD 512
#define CHUNKS 8         // K chunks of 64 fp16 (128B)
#define ROWB 1024        // bytes per packed fp16 row (512 * 2)

// fp16 copy of X (contiguous row-major), filled by prep_kernel each call
__device__ __align__(128) __half g_P[(size_t)NN * DD];
// softplus variance per row (applied to cov diagonal by diag tiles)
__device__ float g_diag[NN];

// ---------------- helpers ----------------
__device__ __forceinline__ uint32_t smem_u32(const void* p) {
    uint32_t a;
    asm("{ .reg .u64 t; cvta.to.shared.u64 t, %1; cvt.u32.u64 %0, t; }"
        : "=r"(a) : "l"(p));
    return a;
}
__device__ __forceinline__ void cp_async16(uint32_t sa, const void* ga) {
    asm volatile("cp.async.cg.shared.global [%0], [%1], 16;" :: "r"(sa), "l"(ga));
}
#define CP_COMMIT() asm volatile("cp.async.commit_group;" ::: "memory")
#define CP_WAIT(n)  asm volatile("cp.async.wait_group %0;" :: "n"(n) : "memory")

#define LDSM4(r0, r1, r2, r3, ad) \
    asm volatile("ldmatrix.sync.aligned.m8n8.x4.shared.b16 {%0,%1,%2,%3}, [%4];" \
                 : "=r"(r0), "=r"(r1), "=r"(r2), "=r"(r3) : "r"(ad))

#define MMA_F16(d, a, b) \
    asm volatile("mma.sync.aligned.m16n8k16.row.col.f32.f16.f16.f32 " \
                 "{%0,%1,%2,%3}, {%4,%5,%6,%7}, {%8,%9}, {%0,%1,%2,%3};" \
                 : "+f"((d)[0]), "+f"((d)[1]), "+f"((d)[2]), "+f"((d)[3]) \
                 : "r"((a)[0]), "r"((a)[1]), "r"((a)[2]), "r"((a)[3]), \
                   "r"((b)[0]), "r"((b)[1]))

#define BARH(idx) asm volatile("bar.sync %0, 128;" :: "r"(idx) : "memory")

// ---------------- fused pre-pass ----------------
__global__ void __launch_bounds__(256)
prep_kernel(const float* __restrict__ X,
            const float* __restrict__ muK,
            const float* __restrict__ varK,
            const float* __restrict__ muB,
            const float* __restrict__ varB,
            float* __restrict__ outMu)
{
    const int row  = blockIdx.x * 8 + (threadIdx.x >> 5);
    const int lane = threadIdx.x & 31;

    const float* xr = X + (size_t)row * DD;
    char* prow = (char*)g_P + (size_t)row * ROWB;

    float smu = 0.0f, sv = 0.0f;
#pragma unroll
    for (int j = 0; j < 4; j++) {
        const int k = lane * 4 + j * 128;
        const float4 xv = *(const float4*)(xr + k);
        const float4 m  = *(const float4*)(muK + k);
        const float4 v  = *(const float4*)(varK + k);
        smu = fmaf(xv.x, m.x, smu); smu = fmaf(xv.y, m.y, smu);
        smu = fmaf(xv.z, m.z, smu); smu = fmaf(xv.w, m.w, smu);
        sv  = fmaf(xv.x, v.x, sv);  sv  = fmaf(xv.y, v.y, sv);
        sv  = fmaf(xv.z, v.z, sv);  sv  = fmaf(xv.w, v.w, sv);

        __half2 p0 = __floats2half2_rn(xv.x, xv.y);
        __half2 p1 = __floats2half2_rn(xv.z, xv.w);
        uint2 w;
        w.x = *(uint32_t*)&p0;
        w.y = *(uint32_t*)&p1;
        *(uint2*)(prow + k * 2) = w;
    }
#pragma unroll
    for (int o = 16; o; o >>= 1) {
        smu += __shfl_xor_sync(0xFFFFFFFFu, smu, o);
        sv  += __shfl_xor_sync(0xFFFFFFFFu, sv, o);
    }
    if (lane == 0) {
        outMu[row] = smu + __ldg(muB);
        const float z = sv + __ldg(varB);
        g_diag[row] = log1pf(expf(z)) + 1e-8f;
    }
}

// ---------------- paired-tile symmetric fp16 HMMA GEMM ----------------
// One 256-thread CTA computes output (128 rows) x (256 cols = 2 tiles),
// sharing the A tile. Warps 0-3 -> left tile, 4-7 -> right tile; each half
// is a 2x2 grid of 64x64 warp tiles.
#define HSTG  49152          // per stage: A 16K + B1 16K + B2 16K
#define NSTAGE 3
#define SMEM_BYTES (1024 + NSTAGE * HSTG)   // 148480
#define EPIT 132             // epilogue stage pitch (floats)
#define HALF_STG_BYTES (128 * EPIT * 4)     // 67584 per half

__global__ void __launch_bounds__(256, 1)
xxt_hmma_kernel(const float* __restrict__ rho_k, float* __restrict__ C)
{
    // ---- decode pair-index -> (r, c0, has2) over upper triangle (64x64 tiles)
    const int bid = blockIdx.x;
    float disc = 4225.0f - 4.0f * (float)bid;
    int t = (int)((65.0f - sqrtf(disc)) * 0.5f);
    if (t < 0) t = 0;
    if (t > 31) t = 31;
    while (t > 0 && t * (65 - t) > bid) t--;
    while ((t + 1) * (65 - (t + 1)) <= bid) t++;
    const int rem = bid - t * (65 - t);
    const int m   = 32 - t;                 // pairs per row in this row-pair
    const int r   = 2 * t + (rem >= m ? 1 : 0);
    const int j   = rem - (rem >= m ? m : 0);
    const int c0  = r + 2 * j;
    const bool has2  = (c0 + 1) < 64;
    const bool diagL = (c0 == r);

    extern __shared__ char sm_raw[];
    const uint32_t raw  = smem_u32(sm_raw);
    const uint32_t base = (raw + 1023) & ~1023u;

    const int tid  = threadIdx.x;
    const int lane = tid & 31;
    const int warp = tid >> 5;
    const int wg   = warp >> 2;            // 0 = left tile, 1 = right tile
    const int wr   = (warp >> 1) & 1;
    const int wc   = warp & 1;
    const bool active = (wg == 0) || has2; // right-half warps idle on singleton

    const int R0   = r * 128;
    const int Ccol = (c0 + wg) * 128;

    float acc[4][8][4];
#pragma unroll
    for (int i = 0; i < 4; i++)
#pragma unroll
        for (int jj = 0; jj < 8; jj++)
#pragma unroll
            for (int k = 0; k < 4; k++) acc[i][jj][k] = 0.0f;

    const char* gp = (const char*)g_P;

#define LOAD_CHUNK(cc, ss)                                                     \
    do {                                                                       \
        const uint32_t sA = base + (ss) * HSTG;                                \
        _Pragma("unroll")                                                      \
        for (int i = 0; i < 4; i++) {                                          \
            const int idx  = i * 256 + tid;                                    \
            const int row  = idx >> 3;                                         \
            const int unit = idx & 7;                                          \
            const uint32_t so =                                                \
                (uint32_t)(row * 128 + ((unit ^ (row & 7)) << 4));             \
            cp_async16(sA + so,                                                \
                       gp + (size_t)(R0 + row) * ROWB + (cc) * 128 + unit*16); \
            if (!diagL)                                                        \
                cp_async16(sA + 16384 + so,                                    \
                           gp + (size_t)(c0 * 128 + row) * ROWB + (cc) * 128 + unit*16); \
            if (has2)                                                          \
                cp_async16(sA + 32768 + so,                                    \
                           gp + (size_t)((c0 + 1) * 128 + row) * ROWB + (cc) * 128 + unit*16); \
        }                                                                      \
        CP_COMMIT();                                                           \
    } while (0)

    LOAD_CHUNK(0, 0);
    LOAD_CHUNK(1, 1);

    for (int c = 0; c < CHUNKS; c++) {
        if (c + 2 < CHUNKS) { CP_WAIT(1); } else { CP_WAIT(0); }
        __syncthreads();   // stage c visible; stage c-1 free to overwrite

        if (c + 2 < CHUNKS) LOAD_CHUNK(c + 2, (c + 2) % NSTAGE);

        const uint32_t bA = base + (c % NSTAGE) * HSTG;
        const uint32_t bB = (wg == 1) ? (bA + 32768)
                                      : (diagL ? bA : (bA + 16384));

#pragma unroll
        for (int ks = 0; ks < 4; ks++) {
            uint32_t aF[4][4], bF[8][2];

            // A fragments: rows wr*64 + mi*16 + (lane&15)
#pragma unroll
            for (int mi = 0; mi < 4; mi++) {
                const int row = wr * 64 + mi * 16 + (lane & 15);
                const int u   = ks * 2 + (lane >> 4);
                const uint32_t ad = bA + row * 128 + ((u ^ (row & 7)) << 4);
                LDSM4(aF[mi][0], aF[mi][1], aF[mi][2], aF[mi][3], ad);
            }
            // B fragments: rows wc*64 + bj*16 + (lane&15)
#pragma unroll
            for (int bj = 0; bj < 4; bj++) {
                const int row = wc * 64 + bj * 16 + (lane & 15);
                const int u   = ks * 2 + (lane >> 4);
                const uint32_t ad = bB + row * 128 + ((u ^ (row & 7)) << 4);
                uint32_t t0, t1, t2, t3;
                LDSM4(t0, t1, t2, t3, ad);
                bF[2 * bj][0] = t0; bF[2 * bj + 1][0] = t1;
                bF[2 * bj][1] = t2; bF[2 * bj + 1][1] = t3;
            }

#pragma unroll
            for (int mi = 0; mi < 4; mi++)
#pragma unroll
                for (int nj = 0; nj < 8; nj++)
                    MMA_F16(acc[mi][nj], aF[mi], bF[nj]);
        }
    }

    // ---------------- epilogue ----------------
    const float s = __ldg(rho_k);

    // Upper tile: direct register stores (skip for inactive right half)
    if (active) {
#pragma unroll
        for (int mi = 0; mi < 4; mi++) {
#pragma unroll
            for (int nj = 0; nj < 8; nj++) {
                const int row = R0 + wr * 64 + mi * 16 + (lane >> 2);
                const int col = Ccol + wc * 64 + nj * 8 + (lane & 3) * 2;
                float2 v0 = make_float2(acc[mi][nj][0] * s, acc[mi][nj][1] * s);
                float2 v1 = make_float2(acc[mi][nj][2] * s, acc[mi][nj][3] * s);
                *(float2*)&C[(size_t)row * NN + col]       = v0;
                *(float2*)&C[(size_t)(row + 8) * NN + col] = v1;
            }
        }
    }

    __syncthreads();   // all MMA smem reads done before staging overwrite

    const bool mirror = active && !(wg == 0 && diagL);
    float* stage = (float*)(sm_raw + (base - raw) + wg * HALF_STG_BYTES);

    if (mirror) {
        // stage scaled tile (half-local coords)
#pragma unroll
        for (int mi = 0; mi < 4; mi++) {
#pragma unroll
            for (int nj = 0; nj < 8; nj++) {
                const int rr  = wr * 64 + mi * 16 + (lane >> 2);
                const int col = wc * 64 + nj * 8 + (lane & 3) * 2;
                float2 v0 = make_float2(acc[mi][nj][0] * s, acc[mi][nj][1] * s);
                float2 v1 = make_float2(acc[mi][nj][2] * s, acc[mi][nj][3] * s);
                *(float2*)&stage[(size_t)rr * EPIT + col]       = v0;
                *(float2*)&stage[(size_t)(rr + 8) * EPIT + col] = v1;
            }
        }
    }
    BARH(1 + wg);      // half-CTA barrier (128 threads)

    if (mirror) {
        const int mcol = tid & 127;   // mirror row = tile col (half-local)
#pragma unroll 8
        for (int jj = 0; jj < 128; jj += 4) {
            float4 v;
            v.x = stage[(size_t)(jj + 0) * EPIT + mcol];
            v.y = stage[(size_t)(jj + 1) * EPIT + mcol];
            v.z = stage[(size_t)(jj + 2) * EPIT + mcol];
            v.w = stage[(size_t)(jj + 3) * EPIT + mcol];
            *(float4*)&C[(size_t)(Ccol + mcol) * NN + R0 + jj] = v;
        }
    } else if (wg == 0 && diagL) {
        // patch the covariance diagonal with the softplus variance
        const int rr = R0 + (tid & 127);
        C[(size_t)rr * NN + rr] = g_diag[rr];
    }
}

extern "C" void kernel_launch(void* const* d_in, const int* in_sizes, int n_in,
                              void* d_out, int out_size)
{
    const float* x     = (const float*)d_in[0];
    const float* mu_k  = (const float*)d_in[1];
    const float* rho_k = (const float*)d_in[2];
    const float* var_k = (const float*)d_in[3];
    const float* mu_b  = (const float*)d_in[4];
    const float* var_b = (const float*)d_in[5];

    float* out_mu = (float*)d_out;
    float* cov    = out_mu + NN;

    cudaFuncSetAttribute(xxt_hmma_kernel,
                         cudaFuncAttributeMaxDynamicSharedMemorySize, SMEM_BYTES);

    prep_kernel<<<NN / 8, 256>>>(x, mu_k, var_k, mu_b, var_b, out_mu);
    xxt_hmma_kernel<<<1056, 256, SMEM_BYTES>>>(rho_k, cov);
}

// round 9
// speedup vs baseline: 1.1129x; 1.1129x over previous
#include <cuda_runtime.h>
#include <cuda_fp16.h>
#include <math.h>
#include <stdint.h>

#define NN 8192
#define DD 512
#define NT 64            // 8192 / 128 tiles per dim
#define CHUNKS 8         // K chunks of 64 fp16 (128B)
#define ROWB 1024        // bytes per packed fp16 row (512 * 2)

// fp16 copy of X (contiguous row-major), filled by prep_kernel each call
__device__ __align__(128) __half g_P[(size_t)NN * DD];
// softplus variance per row (applied to cov diagonal by diag GEMM tiles)
__device__ float g_diag[NN];

// ---------------- helpers ----------------
__device__ __forceinline__ uint32_t smem_u32(const void* p) {
    uint32_t a;
    asm("{ .reg .u64 t; cvta.to.shared.u64 t, %1; cvt.u32.u64 %0, t; }"
        : "=r"(a) : "l"(p));
    return a;
}
__device__ __forceinline__ void cp_async16(uint32_t sa, const void* ga) {
    asm volatile("cp.async.cg.shared.global [%0], [%1], 16;" :: "r"(sa), "l"(ga));
}
#define CP_COMMIT() asm volatile("cp.async.commit_group;" ::: "memory")
#define CP_WAIT(n)  asm volatile("cp.async.wait_group %0;" :: "n"(n) : "memory")

#define LDSM4(r0, r1, r2, r3, ad) \
    asm volatile("ldmatrix.sync.aligned.m8n8.x4.shared.b16 {%0,%1,%2,%3}, [%4];" \
                 : "=r"(r0), "=r"(r1), "=r"(r2), "=r"(r3) : "r"(ad))

#define MMA_F16(d, a, b) \
    asm volatile("mma.sync.aligned.m16n8k16.row.col.f32.f16.f16.f32 " \
                 "{%0,%1,%2,%3}, {%4,%5,%6,%7}, {%8,%9}, {%0,%1,%2,%3};" \
                 : "+f"((d)[0]), "+f"((d)[1]), "+f"((d)[2]), "+f"((d)[3]) \
                 : "r"((a)[0]), "r"((a)[1]), "r"((a)[2]), "r"((a)[3]), \
                   "r"((b)[0]), "r"((b)[1]))

// ---------------- fused pre-pass ----------------
__global__ void __launch_bounds__(256)
prep_kernel(const float* __restrict__ X,
            const float* __restrict__ muK,
            const float* __restrict__ varK,
            const float* __restrict__ muB,
            const float* __restrict__ varB,
            float* __restrict__ outMu)
{
    const int row  = blockIdx.x * 8 + (threadIdx.x >> 5);
    const int lane = threadIdx.x & 31;

    const float* xr = X + (size_t)row * DD;
    char* prow = (char*)g_P + (size_t)row * ROWB;

    float smu = 0.0f, sv = 0.0f;
#pragma unroll
    for (int j = 0; j < 4; j++) {
        const int k = lane * 4 + j * 128;
        const float4 xv = *(const float4*)(xr + k);
        const float4 m  = *(const float4*)(muK + k);
        const float4 v  = *(const float4*)(varK + k);
        smu = fmaf(xv.x, m.x, smu); smu = fmaf(xv.y, m.y, smu);
        smu = fmaf(xv.z, m.z, smu); smu = fmaf(xv.w, m.w, smu);
        sv  = fmaf(xv.x, v.x, sv);  sv  = fmaf(xv.y, v.y, sv);
        sv  = fmaf(xv.z, v.z, sv);  sv  = fmaf(xv.w, v.w, sv);

        __half2 p0 = __floats2half2_rn(xv.x, xv.y);
        __half2 p1 = __floats2half2_rn(xv.z, xv.w);
        uint2 w;
        w.x = *(uint32_t*)&p0;
        w.y = *(uint32_t*)&p1;
        *(uint2*)(prow + k * 2) = w;
    }
#pragma unroll
    for (int o = 16; o; o >>= 1) {
        smu += __shfl_xor_sync(0xFFFFFFFFu, smu, o);
        sv  += __shfl_xor_sync(0xFFFFFFFFu, sv, o);
    }
    if (lane == 0) {
        outMu[row] = smu + __ldg(muB);
        const float z = sv + __ldg(varB);
        g_diag[row] = log1pf(expf(z)) + 1e-8f;
    }
}

// ---------------- symmetric fp16 HMMA GEMM ----------------
// 128x128 CTA tile, 4 warps (2x2) of 64x64 each, fully unrolled chunk loop,
// CTA-dependent ks phase skew to de-correlate co-resident CTAs.
#define STAGE_BYTES 32768
#define NSTAGE 3
#define SMEM_BYTES  (1024 + NSTAGE * STAGE_BYTES)   // 99328
#define EPIT 132              // epilogue stage pitch (floats)

__global__ void __launch_bounds__(128, 2)
xxt_hmma_kernel(const float* __restrict__ rho_k, float* __restrict__ C)
{
    const int tileC = blockIdx.x;
    const int tileR = blockIdx.y;
    if (tileC < tileR) return;
    const bool diag = (tileC == tileR);

    extern __shared__ char sm_raw[];
    const uint32_t raw  = smem_u32(sm_raw);
    const uint32_t base = (raw + 1023) & ~1023u;

    const int tid  = threadIdx.x;
    const int lane = tid & 31;
    const int warp = tid >> 5;
    const int wr   = warp >> 1;   // 0..1
    const int wc   = warp & 1;    // 0..1
    const int hl   = lane >> 4;   // ldmatrix column-half select
    const int l15  = lane & 15;

    // CTA-dependent phase offset so co-resident CTAs hit LDSM/MMA phases
    // at different times (covers the tensor pipe across CTAs).
    const int skew = (tileC + tileR) & 3;

    const int R0 = tileR * 128;
    const int C0 = tileC * 128;

    float acc[4][8][4];
#pragma unroll
    for (int i = 0; i < 4; i++)
#pragma unroll
        for (int j = 0; j < 8; j++)
#pragma unroll
            for (int k = 0; k < 4; k++) acc[i][j][k] = 0.0f;

    const char* gp = (const char*)g_P;

    // Hoisted per-warp fragment row info
    int rowOffA[4], r7A[4], rowOffB[4], r7B[4];
#pragma unroll
    for (int i = 0; i < 4; i++) {
        const int ra = wr * 64 + i * 16 + l15;
        const int rb = wc * 64 + i * 16 + l15;
        rowOffA[i] = ra * 128; r7A[i] = ra & 7;
        rowOffB[i] = rb * 128; r7B[i] = rb & 7;
    }

#define LOAD_CHUNK(cc, ss)                                                     \
    do {                                                                       \
        const uint32_t sb = base + (ss) * STAGE_BYTES;                         \
        _Pragma("unroll")                                                      \
        for (int i = 0; i < 8; i++) {                                          \
            const int idx  = i * 128 + tid;                                    \
            const int row  = idx >> 3;                                         \
            const int unit = idx & 7;                                          \
            const uint32_t so =                                                \
                (uint32_t)(row * 128 + ((unit ^ (row & 7)) << 4));             \
            cp_async16(sb + so,                                                \
                       gp + (size_t)(R0 + row) * ROWB + (cc) * 128 + unit*16); \
            if (!diag)                                                         \
                cp_async16(sb + 16384 + so,                                    \
                           gp + (size_t)(C0 + row) * ROWB + (cc)*128 + unit*16);\
        }                                                                      \
        CP_COMMIT();                                                           \
    } while (0)

    LOAD_CHUNK(0, 0);
    LOAD_CHUNK(1, 1);

#pragma unroll
    for (int c = 0; c < CHUNKS; c++) {
        if (c + 2 < CHUNKS) { CP_WAIT(1); } else { CP_WAIT(0); }
        __syncthreads();   // stage c visible; stage c-1 free to overwrite

        if (c + 2 < CHUNKS) LOAD_CHUNK(c + 2, (c + 2) % NSTAGE);

        const uint32_t bA = base + (c % NSTAGE) * STAGE_BYTES;   // immediate after unroll
        const uint32_t bB = diag ? bA : (bA + 16384);

#pragma unroll
        for (int ksi = 0; ksi < 4; ksi++) {
            const int ks = (ksi + skew) & 3;
            const int u  = ks * 2 + hl;
            uint32_t aF[4][4], bF[8][2];

            // A fragments
#pragma unroll
            for (int mi = 0; mi < 4; mi++) {
                const uint32_t ad = bA + rowOffA[mi] + ((u ^ r7A[mi]) << 4);
                LDSM4(aF[mi][0], aF[mi][1], aF[mi][2], aF[mi][3], ad);
            }
            // B fragments
#pragma unroll
            for (int bj = 0; bj < 4; bj++) {
                const uint32_t ad = bB + rowOffB[bj] + ((u ^ r7B[bj]) << 4);
                uint32_t t0, t1, t2, t3;
                LDSM4(t0, t1, t2, t3, ad);
                bF[2 * bj][0] = t0; bF[2 * bj + 1][0] = t1;
                bF[2 * bj][1] = t2; bF[2 * bj + 1][1] = t3;
            }

#pragma unroll
            for (int mi = 0; mi < 4; mi++)
#pragma unroll
                for (int nj = 0; nj < 8; nj++)
                    MMA_F16(acc[mi][nj], aF[mi], bF[nj]);
        }
    }

    // ---------------- epilogue ----------------
    const float s = __ldg(rho_k);

    // Upper tile: direct register stores
#pragma unroll
    for (int mi = 0; mi < 4; mi++) {
#pragma unroll
        for (int nj = 0; nj < 8; nj++) {
            const int row = R0 + wr * 64 + mi * 16 + (lane >> 2);
            const int col = C0 + wc * 64 + nj * 8 + (lane & 3) * 2;
            float2 v0 = make_float2(acc[mi][nj][0] * s, acc[mi][nj][1] * s);
            float2 v1 = make_float2(acc[mi][nj][2] * s, acc[mi][nj][3] * s);
            *(float2*)&C[(size_t)row * NN + col]       = v0;
            *(float2*)&C[(size_t)(row + 8) * NN + col] = v1;
        }
    }

    if (diag) {
        // patch the covariance diagonal with the softplus variance
        __syncthreads();   // order vs the float2 stores above (CTA scope)
        const int r = R0 + tid;
        C[(size_t)r * NN + r] = g_diag[r];
    } else {
        // Mirror tile (transposed) via full-tile smem staging
        float* stage = (float*)(sm_raw + (base - raw));
        __syncthreads();   // all warps done reading pipeline smem
#pragma unroll
        for (int mi = 0; mi < 4; mi++) {
#pragma unroll
            for (int nj = 0; nj < 8; nj++) {
                const int r   = wr * 64 + mi * 16 + (lane >> 2);
                const int col = wc * 64 + nj * 8 + (lane & 3) * 2;
                float2 v0 = make_float2(acc[mi][nj][0] * s, acc[mi][nj][1] * s);
                float2 v1 = make_float2(acc[mi][nj][2] * s, acc[mi][nj][3] * s);
                *(float2*)&stage[(size_t)r * EPIT + col]       = v0;
                *(float2*)&stage[(size_t)(r + 8) * EPIT + col] = v1;
            }
        }
        __syncthreads();
        const int m = tid;  // mirror row = tile col
#pragma unroll 8
        for (int j = 0; j < 128; j += 4) {
            float4 v;
            v.x = stage[(size_t)(j + 0) * EPIT + m];
            v.y = stage[(size_t)(j + 1) * EPIT + m];
            v.z = stage[(size_t)(j + 2) * EPIT + m];
            v.w = stage[(size_t)(j + 3) * EPIT + m];
            *(float4*)&C[(size_t)(C0 + m) * NN + R0 + j] = v;
        }
    }
}

extern "C" void kernel_launch(void* const* d_in, const int* in_sizes, int n_in,
                              void* d_out, int out_size)
{
    const float* x     = (const float*)d_in[0];
    const float* mu_k  = (const float*)d_in[1];
    const float* rho_k = (const float*)d_in[2];
    const float* var_k = (const float*)d_in[3];
    const float* mu_b  = (const float*)d_in[4];
    const float* var_b = (const float*)d_in[5];

    float* out_mu = (float*)d_out;
    float* cov    = out_mu + NN;

    cudaFuncSetAttribute(xxt_hmma_kernel,
                         cudaFuncAttributeMaxDynamicSharedMemorySize, SMEM_BYTES);

    prep_kernel<<<NN / 8, 256>>>(x, mu_k, var_k, mu_b, var_b, out_mu);
    xxt_hmma_kernel<<<dim3(NT, NT), 128, SMEM_BYTES>>>(rho_k, cov);
}